// round 1
// baseline (speedup 1.0000x reference)
#include <cuda_runtime.h>
#include <cstddef>

// ---------------------------------------------------------------------------
// Problem constants
// ---------------------------------------------------------------------------
#define P_TOTAL (16*64*64)   // 65536 pixels (N*H*W), NHWC with C=256 fastest

// ---------------------------------------------------------------------------
// Scratch (device globals; no cudaMalloc allowed)
// ---------------------------------------------------------------------------
__device__ float g_Veff[256*256];        // composed step1 weights
__device__ float g_ceff[256];            // composed step1 bias
__device__ float g_Y1[(size_t)P_TOTAL*256];   // relu(step1 out)
__device__ float g_Y2[(size_t)P_TOTAL*256];   // step2 out (pre-relu Z blocks)
__device__ float g_base[(size_t)P_TOTAL*64];  // conv3x3(Y1,W2)+b2
__device__ float g_D[(size_t)P_TOTAL*64];     // current delta block
__device__ float g_Acc[(size_t)P_TOTAL*64];   // accumulated corrections

// ---------------------------------------------------------------------------
// Veff composition:  Z_i = x @ V_i + c_i
//   V_i[j,n] = sum_{m<64i} Veff[j,m]*W1[m,n] + (j>=64i ? W1[j,n] : 0)
//   c_i[n]   = sum_{m<64i} ceff[m]*W1[m,n] + b1[n]
// Launched 4x sequentially (i = 0..3). blocks 0..15 -> V, block 16 -> c.
// ---------------------------------------------------------------------------
__global__ void veff_kernel(const float* __restrict__ w1,
                            const float* __restrict__ b1,
                            float* __restrict__ V,
                            float* __restrict__ c,
                            int i)
{
    const int mEnd = i * 64;
    if (blockIdx.x == 16) {
        const int n = threadIdx.x;
        if (n < 64) {
            float s = b1[n];
            for (int m = 0; m < mEnd; ++m) s = fmaf(c[m], w1[m*64 + n], s);
            c[mEnd + n] = s;
        }
        return;
    }
    const int gid = blockIdx.x * 256 + threadIdx.x;   // 0..4095
    const int j  = gid >> 4;                          // 0..255
    const int n0 = (gid & 15) * 4;                    // 0..60
    float4 s = make_float4(0.f, 0.f, 0.f, 0.f);
    if (j >= mEnd) s = *reinterpret_cast<const float4*>(w1 + j*64 + n0);
    for (int m = 0; m < mEnd; ++m) {
        const float vj = V[j*256 + m];
        const float4 w = *reinterpret_cast<const float4*>(w1 + m*64 + n0);
        s.x = fmaf(vj, w.x, s.x);
        s.y = fmaf(vj, w.y, s.y);
        s.z = fmaf(vj, w.z, s.z);
        s.w = fmaf(vj, w.w, s.w);
    }
    *reinterpret_cast<float4*>(V + j*256 + mEnd + n0) = s;
}

// ---------------------------------------------------------------------------
// Unified conv-as-GEMM kernel.
//   out[p, n0+n] (+)= sum_t sum_k in[shift_t(p), k] * W[t*tapStride + k*wNStride + n0+n]
//                     (+ bias) (relu optional)
// Block = one image row (64 px) x 64 out channels. 256 threads, 4x4 per thread.
// ---------------------------------------------------------------------------
template<int TAPS, int CIN>
__global__ void __launch_bounds__(256)
conv_gemm(const float* __restrict__ in,
          const float* __restrict__ W,
          const float* __restrict__ bias,     // may be null
          float* __restrict__ out,
          int wNStride, int outStride, int tapStride,
          int doRelu, int doAccum)
{
    const int rowId = blockIdx.x;        // img*64 + y
    const int y  = rowId & 63;
    const int n0 = blockIdx.y * 64;
    const int tid = threadIdx.x;
    const int tx = tid & 15;             // ch group (4 consecutive)
    const int ty = tid >> 4;             // px group (4 consecutive)
    const int l_kk4 = tid & 3;           // input-load k quad
    const int l_px  = tid >> 2;          // input-load pixel
    const int w_nn4 = tid & 15;          // weight-load n quad
    const int w_kk  = tid >> 4;          // weight-load k

    __shared__ float sIn[16][64];        // [k][px]
    __shared__ float sW[16][64];         // [k][n]

    float acc[4][4];
#pragma unroll
    for (int i = 0; i < 4; ++i)
#pragma unroll
        for (int j = 0; j < 4; ++j) acc[i][j] = 0.f;

#pragma unroll 1
    for (int t = 0; t < TAPS; ++t) {
        const int dy = (TAPS == 9) ? (t / 3 - 1) : 0;
        const int dx = (TAPS == 9) ? (t % 3 - 1) : 0;
        const int ys = y + dy;
        const int xs = l_px + dx;
        const bool valid = (ys >= 0) && (ys < 64) && (xs >= 0) && (xs < 64);
        const float* inP = in + ((size_t)(rowId + dy) * 64 + xs) * CIN;
        const float* wT  = W + (size_t)t * tapStride;

#pragma unroll 1
        for (int kc = 0; kc < CIN / 16; ++kc) {
            float4 v = make_float4(0.f, 0.f, 0.f, 0.f);
            if (valid) v = *reinterpret_cast<const float4*>(inP + kc*16 + l_kk4*4);
            sIn[l_kk4*4 + 0][l_px] = v.x;
            sIn[l_kk4*4 + 1][l_px] = v.y;
            sIn[l_kk4*4 + 2][l_px] = v.z;
            sIn[l_kk4*4 + 3][l_px] = v.w;
            *reinterpret_cast<float4*>(&sW[w_kk][w_nn4*4]) =
                *reinterpret_cast<const float4*>(wT + (size_t)(kc*16 + w_kk)*wNStride + n0 + w_nn4*4);
            __syncthreads();
#pragma unroll
            for (int kk = 0; kk < 16; ++kk) {
                const float4 a = *reinterpret_cast<const float4*>(&sIn[kk][ty*4]);
                const float4 b = *reinterpret_cast<const float4*>(&sW[kk][tx*4]);
                acc[0][0] = fmaf(a.x, b.x, acc[0][0]);
                acc[0][1] = fmaf(a.x, b.y, acc[0][1]);
                acc[0][2] = fmaf(a.x, b.z, acc[0][2]);
                acc[0][3] = fmaf(a.x, b.w, acc[0][3]);
                acc[1][0] = fmaf(a.y, b.x, acc[1][0]);
                acc[1][1] = fmaf(a.y, b.y, acc[1][1]);
                acc[1][2] = fmaf(a.y, b.z, acc[1][2]);
                acc[1][3] = fmaf(a.y, b.w, acc[1][3]);
                acc[2][0] = fmaf(a.z, b.x, acc[2][0]);
                acc[2][1] = fmaf(a.z, b.y, acc[2][1]);
                acc[2][2] = fmaf(a.z, b.z, acc[2][2]);
                acc[2][3] = fmaf(a.z, b.w, acc[2][3]);
                acc[3][0] = fmaf(a.w, b.x, acc[3][0]);
                acc[3][1] = fmaf(a.w, b.y, acc[3][1]);
                acc[3][2] = fmaf(a.w, b.z, acc[3][2]);
                acc[3][3] = fmaf(a.w, b.w, acc[3][3]);
            }
            __syncthreads();
        }
    }

    float4 bv = make_float4(0.f, 0.f, 0.f, 0.f);
    if (bias) bv = *reinterpret_cast<const float4*>(bias + n0 + tx*4);

#pragma unroll
    for (int i = 0; i < 4; ++i) {
        const size_t p = (size_t)rowId * 64 + ty*4 + i;
        float* o = out + p * outStride + n0 + tx*4;
        float4 r;
        r.x = acc[i][0] + bv.x;
        r.y = acc[i][1] + bv.y;
        r.z = acc[i][2] + bv.z;
        r.w = acc[i][3] + bv.w;
        if (doAccum) {
            const float4 old = *reinterpret_cast<const float4*>(o);
            r.x += old.x; r.y += old.y; r.z += old.z; r.w += old.w;
        }
        if (doRelu) {
            r.x = fmaxf(r.x, 0.f); r.y = fmaxf(r.y, 0.f);
            r.z = fmaxf(r.z, 0.f); r.w = fmaxf(r.w, 0.f);
        }
        *reinterpret_cast<float4*>(o) = r;
    }
}

// ---------------------------------------------------------------------------
// Step2 glue:  z = base (+ Acc);  Y2[:, j*64:+64] = z;  if j<3: D = z - Y1_blockj
// one float4 per thread; grid 4096 x 256
// ---------------------------------------------------------------------------
__global__ void epi_kernel(const float* __restrict__ base,
                           const float* __restrict__ acc,
                           const float* __restrict__ Y1,
                           float* __restrict__ Y2,
                           float* __restrict__ D,
                           int j, int useAcc)
{
    const int g = blockIdx.x * 256 + threadIdx.x;   // float4 index, [P*16)
    const size_t p = (size_t)(g >> 4);
    const int c4 = (g & 15) * 4;
    float4 z = reinterpret_cast<const float4*>(base)[g];
    if (useAcc) {
        const float4 a = reinterpret_cast<const float4*>(acc)[g];
        z.x += a.x; z.y += a.y; z.z += a.z; z.w += a.w;
    }
    *reinterpret_cast<float4*>(Y2 + p*256 + j*64 + c4) = z;
    if (j < 3) {
        const float4 yv = *reinterpret_cast<const float4*>(Y1 + p*256 + j*64 + c4);
        float4 d;
        d.x = z.x - yv.x; d.y = z.y - yv.y; d.z = z.z - yv.z; d.w = z.w - yv.w;
        reinterpret_cast<float4*>(D)[g] = d;
    }
}

// ---------------------------------------------------------------------------
// Step3: per-pixel scalar recurrence (replaces 256 sequential 1x1 convs)
//   A0 = relu(Y2);  dot_0 = sum_c A0_c*w3_c
//   z_i = dot_i + b3;  dot_{i+1} = dot_i + (z_i - A0_i)*w3_i
//   out_i = z_i + x_i
// Block = 32 pixels staged in padded smem; 256 threads (32 do the recurrence).
// ---------------------------------------------------------------------------
__global__ void __launch_bounds__(256)
step3_kernel(const float* __restrict__ Y2,
             const float* __restrict__ x,
             const float* __restrict__ w3,
             const float* __restrict__ b3,
             float* __restrict__ out)
{
    __shared__ float sA[32][257];
    __shared__ float sw[256];
    const int tid = threadIdx.x;
    const size_t pBase = (size_t)blockIdx.x * 32;
    sw[tid] = w3[tid];

#pragma unroll
    for (int it = 0; it < 8; ++it) {
        const int g = it * 256 + tid;          // 0..2047
        const int px = g >> 6;
        const int c = (g & 63) * 4;
        const float4 v = *reinterpret_cast<const float4*>(Y2 + (pBase + px)*256 + c);
        sA[px][c + 0] = fmaxf(v.x, 0.f);
        sA[px][c + 1] = fmaxf(v.y, 0.f);
        sA[px][c + 2] = fmaxf(v.z, 0.f);
        sA[px][c + 3] = fmaxf(v.w, 0.f);
    }
    __syncthreads();

    if (tid < 32) {
        float dot = 0.f;
#pragma unroll 8
        for (int c = 0; c < 256; ++c) dot = fmaf(sA[tid][c], sw[c], dot);
        const float bb = b3[0];
#pragma unroll 1
        for (int i = 0; i < 256; ++i) {
            const float a = sA[tid][i];
            const float z = dot + bb;
            sA[tid][i] = z;
            dot = fmaf(z - a, sw[i], dot);
        }
    }
    __syncthreads();

#pragma unroll
    for (int it = 0; it < 8; ++it) {
        const int g = it * 256 + tid;
        const int px = g >> 6;
        const int c = (g & 63) * 4;
        const float4 xv = *reinterpret_cast<const float4*>(x + (pBase + px)*256 + c);
        float4 r;
        r.x = sA[px][c + 0] + xv.x;
        r.y = sA[px][c + 1] + xv.y;
        r.z = sA[px][c + 2] + xv.z;
        r.w = sA[px][c + 3] + xv.w;
        *reinterpret_cast<float4*>(out + (pBase + px)*256 + c) = r;
    }
}

// ---------------------------------------------------------------------------
// Launch
// ---------------------------------------------------------------------------
extern "C" void kernel_launch(void* const* d_in, const int* in_sizes, int n_in,
                              void* d_out, int out_size)
{
    const float* x  = (const float*)d_in[0];
    const float* w1 = (const float*)d_in[1];
    const float* b1 = (const float*)d_in[2];
    const float* w2 = (const float*)d_in[3];
    const float* b2 = (const float*)d_in[4];
    const float* w3 = (const float*)d_in[5];
    const float* b3 = (const float*)d_in[6];
    float* out = (float*)d_out;

    float *Veff, *ceff, *Y1, *Y2, *base, *D, *Acc;
    cudaGetSymbolAddress((void**)&Veff, g_Veff);
    cudaGetSymbolAddress((void**)&ceff, g_ceff);
    cudaGetSymbolAddress((void**)&Y1,   g_Y1);
    cudaGetSymbolAddress((void**)&Y2,   g_Y2);
    cudaGetSymbolAddress((void**)&base, g_base);
    cudaGetSymbolAddress((void**)&D,    g_D);
    cudaGetSymbolAddress((void**)&Acc,  g_Acc);

    // Phase 0: compose step1 into a single effective 256x256 weight matrix
    for (int i = 0; i < 4; ++i)
        veff_kernel<<<17, 256>>>(w1, b1, Veff, ceff, i);

    // Phase 1: Y1 = relu(x @ Veff + ceff)   (one 65536x256x256 GEMM)
    conv_gemm<1, 256><<<dim3(1024, 4), 256>>>(
        x, Veff, ceff, Y1, /*wN*/256, /*outStride*/256, /*tapStride*/0,
        /*relu*/1, /*accum*/0);

    // Phase 2: base = conv3x3(Y1, W2) + b2     (256 -> 64)
    conv_gemm<9, 256><<<dim3(1024, 1), 256>>>(
        Y1, w2, b2, base, 64, 64, /*tapStride*/256*64, 0, 0);

    // Z_0 = base; D_0 = base - Y1[:,0:64]; Y2 block 0
    epi_kernel<<<4096, 256>>>(base, Acc, Y1, Y2, D, 0, 0);

    // Corrections: Z_{j+1} = base + sum_{m<=j} conv3x3(D_m, W2_blockm)
    for (int j = 0; j < 3; ++j) {
        conv_gemm<9, 64><<<dim3(1024, 1), 256>>>(
            D, w2 + (size_t)j*64*64, nullptr, Acc, 64, 64, /*tapStride*/256*64,
            0, /*accum*/(j > 0) ? 1 : 0);
        epi_kernel<<<4096, 256>>>(base, Acc, Y1, Y2, D, j + 1, 1);
    }

    // Phase 3: per-pixel recurrence + residual
    step3_kernel<<<2048, 256>>>(Y2, x, w3, b3, out);
}